// round 1
// baseline (speedup 1.0000x reference)
#include <cuda_runtime.h>

#define NN 100000
#define NE 1600000
#define NG 1024

// ---------------- scratch (static __device__ — no allocation allowed) ----------
__device__ int   g_cnt[NN];        // incoming-edge count per node (excl. self loop)
__device__ int   g_off[NN];        // CSR exclusive offsets
__device__ int   g_fill[NN];       // bucket cursors
__device__ float g_dinv[NN];       // 1/sqrt(deg) (deg incl. self loop)
__device__ int   g_srcs[NE];       // CSR src ids (sorted by dst)
__device__ float g_norm[NE];       // dinv[src]*dinv[dst] per CSR slot
__device__ float g_a1[NN * 4];     // layer-1 pre-projection aggregate
__device__ float g_y1[NN * 64];    // relu(a1 @ W1 + b1)
__device__ float g_a2[NN * 64];    // layer-2 pre-projection aggregate
__device__ float g_pool[NG * 128]; // graph-pooled sums
__device__ int   g_gcnt[NG];       // nodes per graph
__device__ int   g_is64;           // index dtype flag

// ---------------- index dtype handling -----------------------------------------
__device__ __forceinline__ int ld_idx(const void* p, long long i, int is64) {
    return is64 ? (int)((const long long*)p)[i] : ((const int*)p)[i];
}

__global__ void k_detect(const unsigned int* w) {
    if (threadIdx.x == 0 && blockIdx.x == 0) {
        int is64 = 1;
        #pragma unroll 1
        for (int i = 0; i < 256; i++) {
            if (w[2 * i + 1] != 0u) { is64 = 0; break; }
        }
        g_is64 = is64;
    }
}

// ---------------- init ----------------------------------------------------------
__global__ void k_zero() {
    int i = blockIdx.x * blockDim.x + threadIdx.x;
    if (i < NN) { g_cnt[i] = 0; g_fill[i] = 0; }
    if (i < NG * 128) g_pool[i] = 0.0f;
    if (i < NG) g_gcnt[i] = 0;
}

// ---------------- CSR build -----------------------------------------------------
__global__ void k_count(const void* ei, int E) {
    int e = blockIdx.x * blockDim.x + threadIdx.x;
    if (e < E) {
        int is64 = g_is64;
        int d = ld_idx(ei, (long long)E + e, is64);
        atomicAdd(&g_cnt[d], 1);
    }
}

// single-block exclusive scan over g_cnt -> g_off
__global__ void k_scan(int n) {
    __shared__ int sh[1024];
    __shared__ int s_carry;
    int t = threadIdx.x;
    if (t == 0) s_carry = 0;
    __syncthreads();
    for (int base = 0; base < n; base += 1024) {
        int i = base + t;
        int v = (i < n) ? g_cnt[i] : 0;
        sh[t] = v;
        __syncthreads();
        for (int o = 1; o < 1024; o <<= 1) {
            int tv = (t >= o) ? sh[t - o] : 0;
            __syncthreads();
            sh[t] += tv;
            __syncthreads();
        }
        if (i < n) g_off[i] = s_carry + sh[t] - v;  // exclusive
        __syncthreads();
        if (t == 1023) s_carry += sh[1023];
        __syncthreads();
    }
}

__global__ void k_dinv(int n) {
    int i = blockIdx.x * blockDim.x + threadIdx.x;
    if (i < n) g_dinv[i] = rsqrtf((float)(g_cnt[i] + 1));  // +1 = self loop
}

__global__ void k_fill(const void* ei, int E) {
    int e = blockIdx.x * blockDim.x + threadIdx.x;
    if (e < E) {
        int is64 = g_is64;
        int s = ld_idx(ei, e, is64);
        int d = ld_idx(ei, (long long)E + e, is64);
        int slot = g_off[d] + atomicAdd(&g_fill[d], 1);
        g_srcs[slot] = s;
        g_norm[slot] = g_dinv[s] * g_dinv[d];
    }
}

// ---------------- layer 1: aggregate in 4-dim input space ------------------------
__global__ void k_agg1(const float* __restrict__ x, int n) {
    int i = blockIdx.x * blockDim.x + threadIdx.x;
    if (i >= n) return;
    float dn = g_dinv[i];
    float w0 = dn * dn;
    float4 xi = ((const float4*)x)[i];
    float ax = w0 * xi.x, ay = w0 * xi.y, az = w0 * xi.z, aw = w0 * xi.w;
    int b = g_off[i], e = b + g_cnt[i];
    for (int j = b; j < e; j++) {
        int s = g_srcs[j];
        float w = g_norm[j];
        float4 xs = ((const float4*)x)[s];
        ax += w * xs.x; ay += w * xs.y; az += w * xs.z; aw += w * xs.w;
    }
    float4 r; r.x = ax; r.y = ay; r.z = az; r.w = aw;
    ((float4*)g_a1)[i] = r;
}

// y1 = relu(a1 @ W1 + b1)   [NN,4]x[4,64]
__global__ void k_gemm1(const float* __restrict__ W1, const float* __restrict__ b1, int n) {
    __shared__ float sW[256];
    __shared__ float sb[64];
    int t = threadIdx.x;  // 256
    sW[t] = W1[t];
    if (t < 64) sb[t] = b1[t];
    __syncthreads();
    int idx = blockIdx.x * 256 + t;
    if (idx >= n * 64) return;
    int node = idx >> 6, f = idx & 63;
    float4 a = ((const float4*)g_a1)[node];
    float v = fmaf(a.x, sW[f], fmaf(a.y, sW[64 + f], fmaf(a.z, sW[128 + f], a.w * sW[192 + f]))) + sb[f];
    g_y1[idx] = fmaxf(v, 0.0f);
}

// ---------------- layer 2: aggregate in 64-dim space -----------------------------
// blockDim (64,4): 64 feature threads per node, 4 nodes per block
__global__ void k_agg2(int n) {
    int node = blockIdx.x * 4 + threadIdx.y;
    if (node >= n) return;
    int f = threadIdx.x;
    float dn = g_dinv[node];
    float acc = dn * dn * g_y1[node * 64 + f];
    int b = g_off[node], e = b + g_cnt[node];
    int j = b;
    for (; j + 1 < e; j += 2) {
        int s0 = g_srcs[j], s1 = g_srcs[j + 1];
        float w0 = g_norm[j], w1 = g_norm[j + 1];
        acc += w0 * g_y1[s0 * 64 + f];
        acc += w1 * g_y1[s1 * 64 + f];
    }
    if (j < e) acc += g_norm[j] * g_y1[g_srcs[j] * 64 + f];
    g_a2[node * 64 + f] = acc;
}

// ---------------- y2 = relu(a2 @ W2 + b2) fused with graph mean-pool sums --------
// 128 threads (one per output feature), 8 nodes per block
__global__ void k_gemm2pool(const float* __restrict__ W2, const float* __restrict__ b2,
                            const void* __restrict__ batch, int n) {
    __shared__ float sW[64 * 128];
    __shared__ float sA[8][64];
    __shared__ int   sB[8];
    int t = threadIdx.x;  // 128
    for (int i = t; i < 64 * 128; i += 128) sW[i] = W2[i];
    int base = blockIdx.x * 8;
    for (int i = t; i < 8 * 64; i += 128) {
        int q = i >> 6, k = i & 63;
        int nt = base + q;
        sA[q][k] = (nt < n) ? g_a2[nt * 64 + k] : 0.0f;
    }
    if (t < 8) {
        int nt = base + t;
        sB[t] = (nt < n) ? ld_idx(batch, nt, g_is64) : -1;
    }
    __syncthreads();

    float bb = b2[t];
    float acc[8];
    #pragma unroll
    for (int q = 0; q < 8; q++) acc[q] = 0.0f;
    #pragma unroll
    for (int k = 0; k < 64; k++) {
        float w = sW[k * 128 + t];
        #pragma unroll
        for (int q = 0; q < 8; q++) acc[q] = fmaf(sA[q][k], w, acc[q]);
    }

    // relu + bias, then run-length-compressed pooled atomics (batch is sorted)
    float run = 0.0f;
    int cur = -1;
    #pragma unroll
    for (int q = 0; q < 8; q++) {
        int g = sB[q];
        float y = (g >= 0) ? fmaxf(acc[q] + bb, 0.0f) : 0.0f;
        if (g != cur) {
            if (cur >= 0) atomicAdd(&g_pool[cur * 128 + t], run);
            cur = g; run = y;
        } else {
            run += y;
        }
    }
    if (cur >= 0) atomicAdd(&g_pool[cur * 128 + t], run);

    if (t == 0) {
        int rc = 0, cg = -1;
        for (int q = 0; q < 8; q++) {
            int g = sB[q];
            if (g != cg) {
                if (cg >= 0) atomicAdd(&g_gcnt[cg], rc);
                cg = g; rc = (g >= 0) ? 1 : 0;
            } else if (g >= 0) rc++;
        }
        if (cg >= 0) atomicAdd(&g_gcnt[cg], rc);
    }
}

// ---------------- head: mean, fc1+relu, fc2 --------------------------------------
__global__ void k_head(const float* __restrict__ fc1W, const float* __restrict__ fc1b,
                       const float* __restrict__ fc2W, const float* __restrict__ fc2b,
                       float* __restrict__ out) {
    int g = blockIdx.x;
    int t = threadIdx.x;  // 128
    __shared__ float sv[128];
    __shared__ float red[64];
    float denom = fmaxf((float)g_gcnt[g], 1.0f);
    sv[t] = g_pool[g * 128 + t] / denom;
    __syncthreads();
    if (t < 64) {
        float a = fc1b[t];
        #pragma unroll 8
        for (int k = 0; k < 128; k++) a = fmaf(sv[k], fc1W[k * 64 + t], a);
        red[t] = fmaxf(a, 0.0f) * fc2W[t];
    }
    __syncthreads();
    if (t < 32) {
        float v = red[t] + red[t + 32];
        #pragma unroll
        for (int o = 16; o > 0; o >>= 1) v += __shfl_down_sync(0xffffffffu, v, o);
        if (t == 0) out[g] = v + fc2b[0];
    }
}

// ---------------- launch ----------------------------------------------------------
extern "C" void kernel_launch(void* const* d_in, const int* in_sizes, int n_in,
                              void* d_out, int out_size) {
    const float* x     = (const float*)d_in[0];
    const void*  ei    = d_in[1];
    const void*  batch = d_in[2];
    const float* W1    = (const float*)d_in[3];
    const float* b1    = (const float*)d_in[4];
    const float* W2    = (const float*)d_in[5];
    const float* b2    = (const float*)d_in[6];
    const float* fc1W  = (const float*)d_in[7];
    const float* fc1b  = (const float*)d_in[8];
    const float* fc2W  = (const float*)d_in[9];
    const float* fc2b  = (const float*)d_in[10];
    float* out = (float*)d_out;

    int N = in_sizes[0] / 4;   // 100000
    int E = in_sizes[1] / 2;   // 1600000

    k_detect<<<1, 32>>>((const unsigned int*)ei);

    int zmax = NG * 128;  // 131072 > NN
    k_zero<<<(zmax + 255) / 256, 256>>>();

    k_count<<<(E + 511) / 512, 512>>>(ei, E);
    k_scan<<<1, 1024>>>(N);
    k_dinv<<<(N + 255) / 256, 256>>>(N);
    k_fill<<<(E + 511) / 512, 512>>>(ei, E);

    k_agg1<<<(N + 127) / 128, 128>>>(x, N);
    k_gemm1<<<(N * 64 + 255) / 256, 256>>>(W1, b1, N);

    dim3 bt2(64, 4);
    k_agg2<<<(N + 3) / 4, bt2>>>(N);

    k_gemm2pool<<<(N + 7) / 8, 128>>>(W2, b2, batch, N);

    k_head<<<NG, 128>>>(fc1W, fc1b, fc2W, fc2b, out);
}

// round 2
// speedup vs baseline: 1.6657x; 1.6657x over previous
#include <cuda_runtime.h>

#define NN 100000
#define NE 1600000
#define NG 1024
#define SCAN_B 1024
#define NBLK ((NN + SCAN_B - 1) / SCAN_B)   // 98

// ---------------- scratch (static __device__ — no allocation allowed) ----------
__device__ int   g_cnt[NN];        // incoming-edge count per node (excl. self loop)
__device__ int   g_off[NN];        // CSR exclusive offsets
__device__ int   g_fill[NN];       // bucket cursors
__device__ float g_dinv[NN];       // 1/sqrt(deg) (deg incl. self loop)
__device__ int   g_bsum[128];      // per-tile scan partials
__device__ int   g_srcs[NE];       // CSR src ids (sorted by dst)
__device__ float g_norm[NE];       // dinv[src]*dinv[dst] per CSR slot
__device__ float g_a1[NN * 4];     // layer-1 pre-projection aggregate
__device__ float g_y1[NN * 64];    // relu(a1 @ W1 + b1)
__device__ float g_a2[NN * 64];    // layer-2 pre-projection aggregate
__device__ float g_pool[NG * 128]; // graph-pooled sums
__device__ int   g_gcnt[NG];       // nodes per graph
__device__ int   g_is64;           // index dtype flag

// ---------------- index dtype handling -----------------------------------------
__device__ __forceinline__ int ld_idx(const void* p, long long i, int is64) {
    return is64 ? (int)((const long long*)p)[i] : ((const int*)p)[i];
}

__global__ void k_detect(const unsigned int* w) {
    if (threadIdx.x == 0 && blockIdx.x == 0) {
        int is64 = 1;
        #pragma unroll 1
        for (int i = 0; i < 256; i++) {
            if (w[2 * i + 1] != 0u) { is64 = 0; break; }
        }
        g_is64 = is64;
    }
}

// ---------------- init ----------------------------------------------------------
__global__ void k_zero() {
    int i = blockIdx.x * blockDim.x + threadIdx.x;
    if (i < NN) { g_cnt[i] = 0; g_fill[i] = 0; }
    if (i < NG * 128) g_pool[i] = 0.0f;
    if (i < NG) g_gcnt[i] = 0;
}

// ---------------- CSR build -----------------------------------------------------
__global__ void k_count(const void* ei, int E) {
    int e = blockIdx.x * blockDim.x + threadIdx.x;
    if (e < E) {
        int is64 = g_is64;
        int d = ld_idx(ei, (long long)E + e, is64);
        atomicAdd(&g_cnt[d], 1);
    }
}

// grid-wide exclusive scan, phase 1: per-tile warp-shuffle scan + tile sums
__global__ void k_scan1(int n) {
    __shared__ int swarp[32];
    int t = threadIdx.x;
    int i = blockIdx.x * SCAN_B + t;
    int lane = t & 31, wid = t >> 5;
    int v = (i < n) ? g_cnt[i] : 0;
    int s = v;
    #pragma unroll
    for (int o = 1; o < 32; o <<= 1) {
        int u = __shfl_up_sync(0xffffffffu, s, o);
        if (lane >= o) s += u;
    }
    if (lane == 31) swarp[wid] = s;
    __syncthreads();
    if (wid == 0) {
        int ws = swarp[lane];
        #pragma unroll
        for (int o = 1; o < 32; o <<= 1) {
            int u = __shfl_up_sync(0xffffffffu, ws, o);
            if (lane >= o) ws += u;
        }
        swarp[lane] = ws;
    }
    __syncthreads();
    int incl = s + (wid > 0 ? swarp[wid - 1] : 0);
    if (i < n) g_off[i] = incl - v;   // exclusive within tile
    if (t == SCAN_B - 1) g_bsum[blockIdx.x] = incl;
}

// phase 2: scan the (<=128) tile sums in one block
__global__ void k_scan2(int nb) {
    __shared__ int sw[4];
    int t = threadIdx.x;       // 128
    int lane = t & 31, wid = t >> 5;
    int v = (t < nb) ? g_bsum[t] : 0;
    int s = v;
    #pragma unroll
    for (int o = 1; o < 32; o <<= 1) {
        int u = __shfl_up_sync(0xffffffffu, s, o);
        if (lane >= o) s += u;
    }
    if (lane == 31) sw[wid] = s;
    __syncthreads();
    int add = 0;
    #pragma unroll
    for (int w = 0; w < 4; w++) if (w < wid) add += sw[w];
    g_bsum[t] = s - v + add;    // exclusive
}

// phase 3: add tile offsets; fuse dinv computation
__global__ void k_scan3(int n) {
    int i = blockIdx.x * SCAN_B + threadIdx.x;
    if (i < n) {
        g_off[i] += g_bsum[blockIdx.x];
        g_dinv[i] = rsqrtf((float)(g_cnt[i] + 1));   // +1 = self loop
    }
}

__global__ void k_fill(const void* ei, int E) {
    int e = blockIdx.x * blockDim.x + threadIdx.x;
    if (e < E) {
        int is64 = g_is64;
        int s = ld_idx(ei, e, is64);
        int d = ld_idx(ei, (long long)E + e, is64);
        int slot = g_off[d] + atomicAdd(&g_fill[d], 1);
        g_srcs[slot] = s;
        g_norm[slot] = g_dinv[s] * g_dinv[d];
    }
}

// ---------------- layer 1: aggregate in 4-dim input space ------------------------
__global__ void k_agg1(const float* __restrict__ x, int n) {
    int i = blockIdx.x * blockDim.x + threadIdx.x;
    if (i >= n) return;
    float dn = g_dinv[i];
    float w0 = dn * dn;
    float4 xi = ((const float4*)x)[i];
    float ax = w0 * xi.x, ay = w0 * xi.y, az = w0 * xi.z, aw = w0 * xi.w;
    int b = g_off[i], e = b + g_cnt[i];
    for (int j = b; j < e; j++) {
        int s = g_srcs[j];
        float w = g_norm[j];
        float4 xs = __ldg((const float4*)x + s);
        ax += w * xs.x; ay += w * xs.y; az += w * xs.z; aw += w * xs.w;
    }
    float4 r; r.x = ax; r.y = ay; r.z = az; r.w = aw;
    ((float4*)g_a1)[i] = r;
}

// y1 = relu(a1 @ W1 + b1)   [NN,4]x[4,64]
__global__ void k_gemm1(const float* __restrict__ W1, const float* __restrict__ b1, int n) {
    __shared__ float sW[256];
    __shared__ float sb[64];
    int t = threadIdx.x;  // 256
    sW[t] = W1[t];
    if (t < 64) sb[t] = b1[t];
    __syncthreads();
    int idx = blockIdx.x * 256 + t;
    if (idx >= n * 64) return;
    int node = idx >> 6, f = idx & 63;
    float4 a = ((const float4*)g_a1)[node];
    float v = fmaf(a.x, sW[f], fmaf(a.y, sW[64 + f], fmaf(a.z, sW[128 + f], a.w * sW[192 + f]))) + sb[f];
    g_y1[idx] = fmaxf(v, 0.0f);
}

// ---------------- layer 2: aggregate in 64-dim space -----------------------------
// blockDim (64,4): 64 feature threads per node, 4 nodes per block
__global__ void k_agg2(int n) {
    int node = blockIdx.x * 4 + threadIdx.y;
    if (node >= n) return;
    int f = threadIdx.x;
    float dn = g_dinv[node];
    float acc = dn * dn * g_y1[node * 64 + f];
    int b = g_off[node], e = b + g_cnt[node];
    int j = b;
    for (; j + 3 < e; j += 4) {
        int s0 = g_srcs[j],     s1 = g_srcs[j + 1];
        int s2 = g_srcs[j + 2], s3 = g_srcs[j + 3];
        float w0 = g_norm[j],     w1 = g_norm[j + 1];
        float w2 = g_norm[j + 2], w3 = g_norm[j + 3];
        float v0 = __ldg(g_y1 + s0 * 64 + f);
        float v1 = __ldg(g_y1 + s1 * 64 + f);
        float v2 = __ldg(g_y1 + s2 * 64 + f);
        float v3 = __ldg(g_y1 + s3 * 64 + f);
        acc = fmaf(w0, v0, acc);
        acc = fmaf(w1, v1, acc);
        acc = fmaf(w2, v2, acc);
        acc = fmaf(w3, v3, acc);
    }
    for (; j < e; j++) acc = fmaf(g_norm[j], __ldg(g_y1 + g_srcs[j] * 64 + f), acc);
    g_a2[node * 64 + f] = acc;
}

// ---------------- y2 = relu(a2 @ W2 + b2) fused with graph mean-pool sums --------
// 128 threads (one per output feature), 16 nodes per block
#define GP_Q 16
__global__ void k_gemm2pool(const float* __restrict__ W2, const float* __restrict__ b2,
                            const void* __restrict__ batch, int n) {
    __shared__ float sW[64 * 128];
    __shared__ float sA[GP_Q][64];
    __shared__ int   sB[GP_Q];
    int t = threadIdx.x;  // 128
    for (int i = t; i < 64 * 128; i += 128) sW[i] = W2[i];
    int base = blockIdx.x * GP_Q;
    for (int i = t; i < GP_Q * 64; i += 128) {
        int q = i >> 6, k = i & 63;
        int nt = base + q;
        sA[q][k] = (nt < n) ? g_a2[nt * 64 + k] : 0.0f;
    }
    if (t < GP_Q) {
        int nt = base + t;
        sB[t] = (nt < n) ? ld_idx(batch, nt, g_is64) : -1;
    }
    __syncthreads();

    float bb = b2[t];
    float acc[GP_Q];
    #pragma unroll
    for (int q = 0; q < GP_Q; q++) acc[q] = 0.0f;
    #pragma unroll
    for (int k = 0; k < 64; k++) {
        float w = sW[k * 128 + t];
        #pragma unroll
        for (int q = 0; q < GP_Q; q++) acc[q] = fmaf(sA[q][k], w, acc[q]);
    }

    // relu + bias, then run-length-compressed pooled atomics (batch is sorted)
    float run = 0.0f;
    int cur = -1;
    #pragma unroll
    for (int q = 0; q < GP_Q; q++) {
        int g = sB[q];
        float y = (g >= 0) ? fmaxf(acc[q] + bb, 0.0f) : 0.0f;
        if (g != cur) {
            if (cur >= 0) atomicAdd(&g_pool[cur * 128 + t], run);
            cur = g; run = y;
        } else {
            run += y;
        }
    }
    if (cur >= 0) atomicAdd(&g_pool[cur * 128 + t], run);

    if (t == 0) {
        int rc = 0, cg = -1;
        for (int q = 0; q < GP_Q; q++) {
            int g = sB[q];
            if (g != cg) {
                if (cg >= 0) atomicAdd(&g_gcnt[cg], rc);
                cg = g; rc = (g >= 0) ? 1 : 0;
            } else if (g >= 0) rc++;
        }
        if (cg >= 0) atomicAdd(&g_gcnt[cg], rc);
    }
}

// ---------------- head: mean, fc1+relu, fc2 --------------------------------------
__global__ void k_head(const float* __restrict__ fc1W, const float* __restrict__ fc1b,
                       const float* __restrict__ fc2W, const float* __restrict__ fc2b,
                       float* __restrict__ out) {
    int g = blockIdx.x;
    int t = threadIdx.x;  // 128
    __shared__ float sv[128];
    __shared__ float red[64];
    float denom = fmaxf((float)g_gcnt[g], 1.0f);
    sv[t] = g_pool[g * 128 + t] / denom;
    __syncthreads();
    if (t < 64) {
        float a = fc1b[t];
        #pragma unroll 8
        for (int k = 0; k < 128; k++) a = fmaf(sv[k], fc1W[k * 64 + t], a);
        red[t] = fmaxf(a, 0.0f) * fc2W[t];
    }
    __syncthreads();
    if (t < 32) {
        float v = red[t] + red[t + 32];
        #pragma unroll
        for (int o = 16; o > 0; o >>= 1) v += __shfl_down_sync(0xffffffffu, v, o);
        if (t == 0) out[g] = v + fc2b[0];
    }
}

// ---------------- launch ----------------------------------------------------------
extern "C" void kernel_launch(void* const* d_in, const int* in_sizes, int n_in,
                              void* d_out, int out_size) {
    const float* x     = (const float*)d_in[0];
    const void*  ei    = d_in[1];
    const void*  batch = d_in[2];
    const float* W1    = (const float*)d_in[3];
    const float* b1    = (const float*)d_in[4];
    const float* W2    = (const float*)d_in[5];
    const float* b2    = (const float*)d_in[6];
    const float* fc1W  = (const float*)d_in[7];
    const float* fc1b  = (const float*)d_in[8];
    const float* fc2W  = (const float*)d_in[9];
    const float* fc2b  = (const float*)d_in[10];
    float* out = (float*)d_out;

    int N = in_sizes[0] / 4;   // 100000
    int E = in_sizes[1] / 2;   // 1600000

    k_detect<<<1, 32>>>((const unsigned int*)ei);

    int zmax = NG * 128;  // 131072 > NN
    k_zero<<<(zmax + 255) / 256, 256>>>();

    k_count<<<(E + 511) / 512, 512>>>(ei, E);

    int nb = (N + SCAN_B - 1) / SCAN_B;   // 98
    k_scan1<<<nb, SCAN_B>>>(N);
    k_scan2<<<1, 128>>>(nb);
    k_scan3<<<nb, SCAN_B>>>(N);

    k_fill<<<(E + 511) / 512, 512>>>(ei, E);

    k_agg1<<<(N + 127) / 128, 128>>>(x, N);
    k_gemm1<<<(N * 64 + 255) / 256, 256>>>(W1, b1, N);

    dim3 bt2(64, 4);
    k_agg2<<<(N + 3) / 4, bt2>>>(N);

    k_gemm2pool<<<(N + GP_Q - 1) / GP_Q, 128>>>(W2, b2, batch, N);

    k_head<<<NG, 128>>>(fc1W, fc1b, fc2W, fc2b, out);
}

// round 3
// speedup vs baseline: 2.2500x; 1.3508x over previous
#include <cuda_runtime.h>
#include <cuda_fp16.h>

#define NN 100000
#define NE 1600000
#define NG 1024
#define SCAN_B 1024

// ---------------- scratch (static __device__ — no allocation allowed) ----------
__device__ int    g_cnt[NN];        // incoming-edge count per node (excl. self loop)
__device__ int    g_off[NN];        // CSR exclusive offsets
__device__ int    g_fill[NN];       // bucket cursors
__device__ float  g_dinv[NN];       // 1/sqrt(deg) (deg incl. self loop)
__device__ int    g_bsum[128];      // per-tile scan partials
__device__ float2 g_csr[NE];        // packed CSR: {src-as-float-bits, norm}
__device__ float  g_a1[NN * 4];     // layer-1 pre-projection aggregate
__device__ __half g_y1h[NN * 64];   // relu(a1 @ W1 + b1) in fp16
__device__ float  g_a2[NN * 64];    // layer-2 pre-projection aggregate
__device__ float  g_pool[NG * 128]; // graph-pooled sums
__device__ int    g_gcnt[NG];       // nodes per graph
__device__ int    g_is64;           // index dtype flag

// ---------------- index dtype handling -----------------------------------------
__device__ __forceinline__ int ld_idx(const void* p, long long i, int is64) {
    return is64 ? (int)((const long long*)p)[i] : ((const int*)p)[i];
}

__global__ void k_detect(const unsigned int* w) {
    if (threadIdx.x == 0 && blockIdx.x == 0) {
        int is64 = 1;
        #pragma unroll 1
        for (int i = 0; i < 256; i++) {
            if (w[2 * i + 1] != 0u) { is64 = 0; break; }
        }
        g_is64 = is64;
    }
}

// ---------------- init ----------------------------------------------------------
__global__ void k_zero() {
    int i = blockIdx.x * blockDim.x + threadIdx.x;
    if (i < NN) { g_cnt[i] = 0; g_fill[i] = 0; }
    if (i < NG * 128) g_pool[i] = 0.0f;
    if (i < NG) g_gcnt[i] = 0;
}

// ---------------- CSR build -----------------------------------------------------
__global__ void k_count(const void* ei, int E) {
    int e = blockIdx.x * blockDim.x + threadIdx.x;
    if (e < E) {
        int is64 = g_is64;
        int d = ld_idx(ei, (long long)E + e, is64);
        atomicAdd(&g_cnt[d], 1);
    }
}

// grid-wide exclusive scan, phase 1: per-tile warp-shuffle scan + tile sums
__global__ void k_scan1(int n) {
    __shared__ int swarp[32];
    int t = threadIdx.x;
    int i = blockIdx.x * SCAN_B + t;
    int lane = t & 31, wid = t >> 5;
    int v = (i < n) ? g_cnt[i] : 0;
    int s = v;
    #pragma unroll
    for (int o = 1; o < 32; o <<= 1) {
        int u = __shfl_up_sync(0xffffffffu, s, o);
        if (lane >= o) s += u;
    }
    if (lane == 31) swarp[wid] = s;
    __syncthreads();
    if (wid == 0) {
        int ws = swarp[lane];
        #pragma unroll
        for (int o = 1; o < 32; o <<= 1) {
            int u = __shfl_up_sync(0xffffffffu, ws, o);
            if (lane >= o) ws += u;
        }
        swarp[lane] = ws;
    }
    __syncthreads();
    int incl = s + (wid > 0 ? swarp[wid - 1] : 0);
    if (i < n) g_off[i] = incl - v;   // exclusive within tile
    if (t == SCAN_B - 1) g_bsum[blockIdx.x] = incl;
}

// phase 2: scan the (<=128) tile sums in one block
__global__ void k_scan2(int nb) {
    __shared__ int sw[4];
    int t = threadIdx.x;       // 128
    int lane = t & 31, wid = t >> 5;
    int v = (t < nb) ? g_bsum[t] : 0;
    int s = v;
    #pragma unroll
    for (int o = 1; o < 32; o <<= 1) {
        int u = __shfl_up_sync(0xffffffffu, s, o);
        if (lane >= o) s += u;
    }
    if (lane == 31) sw[wid] = s;
    __syncthreads();
    int add = 0;
    #pragma unroll
    for (int w = 0; w < 4; w++) if (w < wid) add += sw[w];
    g_bsum[t] = s - v + add;    // exclusive
}

// phase 3: add tile offsets; fuse dinv computation
__global__ void k_scan3(int n) {
    int i = blockIdx.x * SCAN_B + threadIdx.x;
    if (i < n) {
        g_off[i] += g_bsum[blockIdx.x];
        g_dinv[i] = rsqrtf((float)(g_cnt[i] + 1));   // +1 = self loop
    }
}

__global__ void k_fill(const void* ei, int E) {
    int e = blockIdx.x * blockDim.x + threadIdx.x;
    if (e < E) {
        int is64 = g_is64;
        int s = ld_idx(ei, e, is64);
        int d = ld_idx(ei, (long long)E + e, is64);
        int slot = g_off[d] + atomicAdd(&g_fill[d], 1);
        float2 c; c.x = __int_as_float(s); c.y = g_dinv[s] * g_dinv[d];
        g_csr[slot] = c;
    }
}

// ---------------- layer 1: aggregate in 4-dim input space ------------------------
__global__ void k_agg1(const float* __restrict__ x, int n) {
    int i = blockIdx.x * blockDim.x + threadIdx.x;
    if (i >= n) return;
    float dn = g_dinv[i];
    float w0 = dn * dn;
    float4 xi = ((const float4*)x)[i];
    float ax = w0 * xi.x, ay = w0 * xi.y, az = w0 * xi.z, aw = w0 * xi.w;
    int b = g_off[i], e = b + g_cnt[i];
    for (int j = b; j < e; j++) {
        float2 c = g_csr[j];
        int s = __float_as_int(c.x);
        float w = c.y;
        float4 xs = __ldg((const float4*)x + s);
        ax = fmaf(w, xs.x, ax); ay = fmaf(w, xs.y, ay);
        az = fmaf(w, xs.z, az); aw = fmaf(w, xs.w, aw);
    }
    float4 r; r.x = ax; r.y = ay; r.z = az; r.w = aw;
    ((float4*)g_a1)[i] = r;
}

// y1 = relu(a1 @ W1 + b1)   [NN,4]x[4,64] -> fp16, each thread emits a half2
__global__ void k_gemm1(const float* __restrict__ W1, const float* __restrict__ b1, int n) {
    __shared__ float sW[256];
    __shared__ float sb[64];
    int t = threadIdx.x;  // 256
    sW[t] = W1[t];
    if (t < 64) sb[t] = b1[t];
    __syncthreads();
    int idx = blockIdx.x * 256 + t;
    if (idx >= n * 32) return;
    int node = idx >> 5, f = (idx & 31) * 2;
    float4 a = ((const float4*)g_a1)[node];
    float v0 = fmaf(a.x, sW[f],     fmaf(a.y, sW[64 + f],     fmaf(a.z, sW[128 + f],     a.w * sW[192 + f])))     + sb[f];
    float v1 = fmaf(a.x, sW[f + 1], fmaf(a.y, sW[64 + f + 1], fmaf(a.z, sW[128 + f + 1], a.w * sW[192 + f + 1]))) + sb[f + 1];
    ((__half2*)g_y1h)[idx] = __floats2half2_rn(fmaxf(v0, 0.0f), fmaxf(v1, 0.0f));
}

// ---------------- layer 2: aggregate in 64-dim fp16 space -------------------------
// blockDim (32,8): 32 threads per node, each owning 2 features (half2); 8 nodes/block
__global__ void k_agg2(int n) {
    int node = blockIdx.x * 8 + threadIdx.y;
    if (node >= n) return;
    int t = threadIdx.x;   // 0..31
    const __half2* __restrict__ y1 = (const __half2*)g_y1h;
    float dn = g_dinv[node];
    float w0 = dn * dn;
    float2 sf = __half22float2(y1[(node << 5) + t]);
    float2 acc; acc.x = w0 * sf.x; acc.y = w0 * sf.y;
    int b = g_off[node], e = b + g_cnt[node];
    int j = b;
    for (; j + 3 < e; j += 4) {
        float2 c0 = g_csr[j],     c1 = g_csr[j + 1];
        float2 c2 = g_csr[j + 2], c3 = g_csr[j + 3];
        __half2 v0 = __ldg(y1 + (__float_as_int(c0.x) << 5) + t);
        __half2 v1 = __ldg(y1 + (__float_as_int(c1.x) << 5) + t);
        __half2 v2 = __ldg(y1 + (__float_as_int(c2.x) << 5) + t);
        __half2 v3 = __ldg(y1 + (__float_as_int(c3.x) << 5) + t);
        float2 f0 = __half22float2(v0), f1 = __half22float2(v1);
        float2 f2 = __half22float2(v2), f3 = __half22float2(v3);
        acc.x = fmaf(c0.y, f0.x, acc.x); acc.y = fmaf(c0.y, f0.y, acc.y);
        acc.x = fmaf(c1.y, f1.x, acc.x); acc.y = fmaf(c1.y, f1.y, acc.y);
        acc.x = fmaf(c2.y, f2.x, acc.x); acc.y = fmaf(c2.y, f2.y, acc.y);
        acc.x = fmaf(c3.y, f3.x, acc.x); acc.y = fmaf(c3.y, f3.y, acc.y);
    }
    for (; j < e; j++) {
        float2 c = g_csr[j];
        float2 f = __half22float2(__ldg(y1 + (__float_as_int(c.x) << 5) + t));
        acc.x = fmaf(c.y, f.x, acc.x); acc.y = fmaf(c.y, f.y, acc.y);
    }
    ((float2*)g_a2)[(node << 5) + t] = acc;
}

// ---------------- y2 = relu(a2 @ W2 + b2) fused with graph mean-pool sums --------
// 256 threads, 32 nodes/block. Thread tile: 4 nodes x 4 features, f32x2 packed FMA.
#define MB 32
#define AT_STRIDE 36
__global__ void k_gemm2pool(const float* __restrict__ W2, const float* __restrict__ b2,
                            const void* __restrict__ batch, int n) {
    __shared__ float sW[64 * 128];          // 32 KB
    __shared__ float sAT[64 * AT_STRIDE];   // 9 KB  (transposed a2: [k][node])
    __shared__ int   sB[MB];
    int t = threadIdx.x;  // 256
    for (int i = t; i < 64 * 128; i += 256) sW[i] = W2[i];
    int base = blockIdx.x * MB;
    for (int i = t; i < MB * 64; i += 256) {
        int nl = i >> 6, k = i & 63;
        int nt = base + nl;
        sAT[k * AT_STRIDE + nl] = (nt < n) ? g_a2[nt * 64 + k] : 0.0f;
    }
    if (t < MB) {
        int nt = base + t;
        sB[t] = (nt < n) ? ld_idx(batch, nt, g_is64) : -1;
    }
    __syncthreads();

    int tx = t & 31;   // feature group: features tx*4 .. tx*4+3
    int ty = t >> 5;   // node group:    nodes ty*4 .. ty*4+3 (local)

    unsigned long long accp[4][2];   // [node q][feature pair]
    #pragma unroll
    for (int q = 0; q < 4; q++) { accp[q][0] = 0ull; accp[q][1] = 0ull; }

    #pragma unroll 4
    for (int k = 0; k < 64; k++) {
        float4 wv = *(const float4*)&sW[k * 128 + tx * 4];
        float4 av = *(const float4*)&sAT[k * AT_STRIDE + ty * 4];
        ulonglong2 wp = *reinterpret_cast<ulonglong2*>(&wv);   // {w0,w1},{w2,w3}
        float aq[4] = {av.x, av.y, av.z, av.w};
        #pragma unroll
        for (int q = 0; q < 4; q++) {
            unsigned long long ad;
            asm("mov.b64 %0, {%1, %1};" : "=l"(ad) : "f"(aq[q]));
            asm("fma.rn.f32x2 %0, %1, %2, %0;" : "+l"(accp[q][0]) : "l"(ad), "l"(wp.x));
            asm("fma.rn.f32x2 %0, %1, %2, %0;" : "+l"(accp[q][1]) : "l"(ad), "l"(wp.y));
        }
    }

    float bias0 = b2[tx * 4], bias1 = b2[tx * 4 + 1];
    float bias2 = b2[tx * 4 + 2], bias3 = b2[tx * 4 + 3];

    // unpack + relu
    float y[4][4];
    #pragma unroll
    for (int q = 0; q < 4; q++) {
        float l0, h0, l1, h1;
        asm("mov.b64 {%0, %1}, %2;" : "=f"(l0), "=f"(h0) : "l"(accp[q][0]));
        asm("mov.b64 {%0, %1}, %2;" : "=f"(l1), "=f"(h1) : "l"(accp[q][1]));
        y[q][0] = fmaxf(l0 + bias0, 0.0f);
        y[q][1] = fmaxf(h0 + bias1, 0.0f);
        y[q][2] = fmaxf(l1 + bias2, 0.0f);
        y[q][3] = fmaxf(h1 + bias3, 0.0f);
    }

    // run-length pooled atomics over this thread's 4 (sorted-batch) nodes
    int cur = -1;
    float run0 = 0, run1 = 0, run2 = 0, run3 = 0;
    #pragma unroll
    for (int q = 0; q < 4; q++) {
        int g = sB[ty * 4 + q];
        if (g != cur) {
            if (cur >= 0) {
                float* p = &g_pool[cur * 128 + tx * 4];
                atomicAdd(p, run0); atomicAdd(p + 1, run1);
                atomicAdd(p + 2, run2); atomicAdd(p + 3, run3);
            }
            cur = g; run0 = y[q][0]; run1 = y[q][1]; run2 = y[q][2]; run3 = y[q][3];
        } else {
            run0 += y[q][0]; run1 += y[q][1]; run2 += y[q][2]; run3 += y[q][3];
        }
    }
    if (cur >= 0) {
        float* p = &g_pool[cur * 128 + tx * 4];
        atomicAdd(p, run0); atomicAdd(p + 1, run1);
        atomicAdd(p + 2, run2); atomicAdd(p + 3, run3);
    }

    if (t == 0) {
        int rc = 0, cg = -1;
        for (int q = 0; q < MB; q++) {
            int g = sB[q];
            if (g != cg) {
                if (cg >= 0) atomicAdd(&g_gcnt[cg], rc);
                cg = g; rc = (g >= 0) ? 1 : 0;
            } else if (g >= 0) rc++;
        }
        if (cg >= 0) atomicAdd(&g_gcnt[cg], rc);
    }
}

// ---------------- head: mean, fc1+relu, fc2 --------------------------------------
__global__ void k_head(const float* __restrict__ fc1W, const float* __restrict__ fc1b,
                       const float* __restrict__ fc2W, const float* __restrict__ fc2b,
                       float* __restrict__ out) {
    int g = blockIdx.x;
    int t = threadIdx.x;  // 128
    __shared__ float sv[128];
    __shared__ float red[64];
    float denom = fmaxf((float)g_gcnt[g], 1.0f);
    sv[t] = g_pool[g * 128 + t] / denom;
    __syncthreads();
    if (t < 64) {
        float a = fc1b[t];
        #pragma unroll 8
        for (int k = 0; k < 128; k++) a = fmaf(sv[k], fc1W[k * 64 + t], a);
        red[t] = fmaxf(a, 0.0f) * fc2W[t];
    }
    __syncthreads();
    if (t < 32) {
        float v = red[t] + red[t + 32];
        #pragma unroll
        for (int o = 16; o > 0; o >>= 1) v += __shfl_down_sync(0xffffffffu, v, o);
        if (t == 0) out[g] = v + fc2b[0];
    }
}

// ---------------- launch ----------------------------------------------------------
extern "C" void kernel_launch(void* const* d_in, const int* in_sizes, int n_in,
                              void* d_out, int out_size) {
    const float* x     = (const float*)d_in[0];
    const void*  ei    = d_in[1];
    const void*  batch = d_in[2];
    const float* W1    = (const float*)d_in[3];
    const float* b1    = (const float*)d_in[4];
    const float* W2    = (const float*)d_in[5];
    const float* b2    = (const float*)d_in[6];
    const float* fc1W  = (const float*)d_in[7];
    const float* fc1b  = (const float*)d_in[8];
    const float* fc2W  = (const float*)d_in[9];
    const float* fc2b  = (const float*)d_in[10];
    float* out = (float*)d_out;

    int N = in_sizes[0] / 4;   // 100000
    int E = in_sizes[1] / 2;   // 1600000

    k_detect<<<1, 32>>>((const unsigned int*)ei);

    int zmax = NG * 128;  // 131072 > NN
    k_zero<<<(zmax + 255) / 256, 256>>>();

    k_count<<<(E + 511) / 512, 512>>>(ei, E);

    int nb = (N + SCAN_B - 1) / SCAN_B;   // 98
    k_scan1<<<nb, SCAN_B>>>(N);
    k_scan2<<<1, 128>>>(nb);
    k_scan3<<<nb, SCAN_B>>>(N);

    k_fill<<<(E + 511) / 512, 512>>>(ei, E);

    k_agg1<<<(N + 127) / 128, 128>>>(x, N);
    k_gemm1<<<(N * 32 + 255) / 256, 256>>>(W1, b1, N);

    dim3 bt2(32, 8);
    k_agg2<<<(N + 7) / 8, bt2>>>(N);

    k_gemm2pool<<<(N + MB - 1) / MB, 256>>>(W2, b2, batch, N);

    k_head<<<NG, 128>>>(fc1W, fc1b, fc2W, fc2b, out);
}

// round 4
// speedup vs baseline: 2.8319x; 1.2586x over previous
#include <cuda_runtime.h>
#include <cuda_fp16.h>

#define NN 100000
#define NE 1600000
#define NG 1024
#define SCAN_B 1024

// ---------------- scratch (static __device__ — no allocation allowed) ----------
__device__ int    g_cnt[NN];        // incoming-edge count per node (excl. self loop)
__device__ int    g_off[NN];        // CSR exclusive offsets
__device__ int    g_fill[NN];       // bucket cursors
__device__ float  g_dinv[NN];       // 1/sqrt(deg) (deg incl. self loop)
__device__ int    g_bsum[128];      // per-tile scan partials
__device__ int    g_srcs[NE];       // CSR src ids (sorted by dst)
__device__ float  g_xs[NN * 4];     // dinv-prescaled input features
__device__ __half g_y1h[NN * 64];   // dinv * relu(a1 @ W1 + b1)  (layer-2 pre-scaled)
__device__ float  g_a2[NN * 64];    // layer-2 pre-projection aggregate
__device__ float  g_pool[NG * 128]; // graph-pooled sums
__device__ int    g_gcnt[NG];       // nodes per graph
__device__ int    g_is64;           // index dtype flag

// ---------------- index dtype handling -----------------------------------------
__device__ __forceinline__ int ld_idx(const void* p, long long i, int is64) {
    return is64 ? (int)((const long long*)p)[i] : ((const int*)p)[i];
}

__global__ void k_detect(const unsigned int* w) {
    if (threadIdx.x == 0 && blockIdx.x == 0) {
        int is64 = 1;
        #pragma unroll 1
        for (int i = 0; i < 256; i++) {
            if (w[2 * i + 1] != 0u) { is64 = 0; break; }
        }
        g_is64 = is64;
    }
}

// ---------------- init ----------------------------------------------------------
__global__ void k_zero() {
    int i = blockIdx.x * blockDim.x + threadIdx.x;
    if (i < NN) { g_cnt[i] = 0; g_fill[i] = 0; }
    if (i < NG * 128) g_pool[i] = 0.0f;
    if (i < NG) g_gcnt[i] = 0;
}

// ---------------- CSR build -----------------------------------------------------
__global__ void k_count(const void* ei, int E) {
    int e = blockIdx.x * blockDim.x + threadIdx.x;
    if (e < E) {
        int is64 = g_is64;
        int d = ld_idx(ei, (long long)E + e, is64);
        atomicAdd(&g_cnt[d], 1);
    }
}

// grid-wide exclusive scan, phase 1: per-tile warp-shuffle scan + tile sums
__global__ void k_scan1(int n) {
    __shared__ int swarp[32];
    int t = threadIdx.x;
    int i = blockIdx.x * SCAN_B + t;
    int lane = t & 31, wid = t >> 5;
    int v = (i < n) ? g_cnt[i] : 0;
    int s = v;
    #pragma unroll
    for (int o = 1; o < 32; o <<= 1) {
        int u = __shfl_up_sync(0xffffffffu, s, o);
        if (lane >= o) s += u;
    }
    if (lane == 31) swarp[wid] = s;
    __syncthreads();
    if (wid == 0) {
        int ws = swarp[lane];
        #pragma unroll
        for (int o = 1; o < 32; o <<= 1) {
            int u = __shfl_up_sync(0xffffffffu, ws, o);
            if (lane >= o) ws += u;
        }
        swarp[lane] = ws;
    }
    __syncthreads();
    int incl = s + (wid > 0 ? swarp[wid - 1] : 0);
    if (i < n) g_off[i] = incl - v;   // exclusive within tile
    if (t == SCAN_B - 1) g_bsum[blockIdx.x] = incl;
}

// phase 2: scan the (<=128) tile sums in one block
__global__ void k_scan2(int nb) {
    __shared__ int sw[4];
    int t = threadIdx.x;       // 128
    int lane = t & 31, wid = t >> 5;
    int v = (t < nb) ? g_bsum[t] : 0;
    int s = v;
    #pragma unroll
    for (int o = 1; o < 32; o <<= 1) {
        int u = __shfl_up_sync(0xffffffffu, s, o);
        if (lane >= o) s += u;
    }
    if (lane == 31) sw[wid] = s;
    __syncthreads();
    int add = 0;
    #pragma unroll
    for (int w = 0; w < 4; w++) if (w < wid) add += sw[w];
    g_bsum[t] = s - v + add;    // exclusive
}

// phase 3: add tile offsets; compute dinv; prescale x by dinv
__global__ void k_scan3(const float* __restrict__ x, int n) {
    int i = blockIdx.x * SCAN_B + threadIdx.x;
    if (i < n) {
        g_off[i] += g_bsum[blockIdx.x];
        float dn = rsqrtf((float)(g_cnt[i] + 1));   // +1 = self loop
        g_dinv[i] = dn;
        float4 xi = ((const float4*)x)[i];
        float4 r; r.x = dn * xi.x; r.y = dn * xi.y; r.z = dn * xi.z; r.w = dn * xi.w;
        ((float4*)g_xs)[i] = r;
    }
}

__global__ void k_fill(const void* ei, int E) {
    int e = blockIdx.x * blockDim.x + threadIdx.x;
    if (e < E) {
        int is64 = g_is64;
        int s = ld_idx(ei, e, is64);
        int d = ld_idx(ei, (long long)E + e, is64);
        int slot = g_off[d] + atomicAdd(&g_fill[d], 1);
        g_srcs[slot] = s;
    }
}

// ---------------- fused layer 1: gather-sum (4-dim) + W1 projection + relu -------
// y1h[i] = dinv[i] * relu( (dinv[i] * Σ xs[nbr∪self]) @ W1 + b1 )  stored fp16
__global__ void k_l1(const float* __restrict__ W1, const float* __restrict__ b1, int n) {
    __shared__ float sW[256];
    __shared__ float sb[64];
    int t = threadIdx.x;  // 128
    sW[t] = W1[t]; sW[t + 128] = W1[t + 128];
    if (t < 64) sb[t] = b1[t];
    __syncthreads();
    int i = blockIdx.x * 128 + t;
    if (i >= n) return;
    const float4* __restrict__ xs = (const float4*)g_xs;
    float4 a = xs[i];   // self term (already dinv-scaled)
    int b = g_off[i], e = b + g_cnt[i];
    int j = b;
    for (; j + 3 < e; j += 4) {
        int s0 = g_srcs[j],     s1 = g_srcs[j + 1];
        int s2 = g_srcs[j + 2], s3 = g_srcs[j + 3];
        float4 v0 = __ldg(xs + s0), v1 = __ldg(xs + s1);
        float4 v2 = __ldg(xs + s2), v3 = __ldg(xs + s3);
        a.x += (v0.x + v1.x) + (v2.x + v3.x);
        a.y += (v0.y + v1.y) + (v2.y + v3.y);
        a.z += (v0.z + v1.z) + (v2.z + v3.z);
        a.w += (v0.w + v1.w) + (v2.w + v3.w);
    }
    for (; j < e; j++) {
        float4 v = __ldg(xs + g_srcs[j]);
        a.x += v.x; a.y += v.y; a.z += v.z; a.w += v.w;
    }
    float dn = g_dinv[i];
    a.x *= dn; a.y *= dn; a.z *= dn; a.w *= dn;

    uint4* yo = (uint4*)(g_y1h + i * 64);   // 8 x uint4 = 64 halves
    #pragma unroll
    for (int fg = 0; fg < 8; fg++) {
        uint4 st;
        unsigned* sp = (unsigned*)&st;
        #pragma unroll
        for (int p = 0; p < 4; p++) {
            int f = fg * 8 + p * 2;
            float v0 = fmaf(a.x, sW[f],     fmaf(a.y, sW[64 + f],     fmaf(a.z, sW[128 + f],     a.w * sW[192 + f])))     + sb[f];
            float v1 = fmaf(a.x, sW[f + 1], fmaf(a.y, sW[64 + f + 1], fmaf(a.z, sW[128 + f + 1], a.w * sW[192 + f + 1]))) + sb[f + 1];
            __half2 h = __floats2half2_rn(fmaxf(v0, 0.0f) * dn, fmaxf(v1, 0.0f) * dn);
            sp[p] = *(unsigned*)&h;
        }
        yo[fg] = st;
    }
}

// ---------------- layer 2: unweighted gather-sum in 64-dim fp16 space ------------
// blockDim (32,8): 32 threads per node, each owning 2 features (half2); 8 nodes/block
__global__ void k_agg2(int n) {
    int node = blockIdx.x * 8 + threadIdx.y;
    if (node >= n) return;
    int t = threadIdx.x;   // 0..31
    const __half2* __restrict__ y1 = (const __half2*)g_y1h;
    float2 acc = __half22float2(y1[(node << 5) + t]);   // self term (pre-scaled)
    int b = g_off[node], e = b + g_cnt[node];
    int j = b;
    for (; j + 3 < e; j += 4) {
        int s0 = g_srcs[j],     s1 = g_srcs[j + 1];
        int s2 = g_srcs[j + 2], s3 = g_srcs[j + 3];
        float2 f0 = __half22float2(__ldg(y1 + (s0 << 5) + t));
        float2 f1 = __half22float2(__ldg(y1 + (s1 << 5) + t));
        float2 f2 = __half22float2(__ldg(y1 + (s2 << 5) + t));
        float2 f3 = __half22float2(__ldg(y1 + (s3 << 5) + t));
        acc.x += (f0.x + f1.x) + (f2.x + f3.x);
        acc.y += (f0.y + f1.y) + (f2.y + f3.y);
    }
    for (; j < e; j++) {
        float2 f = __half22float2(__ldg(y1 + (g_srcs[j] << 5) + t));
        acc.x += f.x; acc.y += f.y;
    }
    float dn = g_dinv[node];
    acc.x *= dn; acc.y *= dn;
    ((float2*)g_a2)[(node << 5) + t] = acc;
}

// ---------------- y2 = relu(a2 @ W2 + b2) fused with graph mean-pool sums --------
// 256 threads, 64 nodes/block. Thread tile: 8 nodes x 4 features, f32x2 packed FMA.
#define MB 64
#define NQ 8
#define AT_STRIDE 68
__global__ void k_gemm2pool(const float* __restrict__ W2, const float* __restrict__ b2,
                            const void* __restrict__ batch, int n) {
    __shared__ float sW[64 * 128];          // 32 KB
    __shared__ float sAT[64 * AT_STRIDE];   // 17 KB  (transposed a2: [k][node])
    __shared__ int   sB[MB];
    int t = threadIdx.x;  // 256
    for (int i = t; i < 64 * 128; i += 256) sW[i] = W2[i];
    int base = blockIdx.x * MB;
    for (int i = t; i < MB * 64; i += 256) {
        int nl = i >> 6, k = i & 63;
        int nt = base + nl;
        sAT[k * AT_STRIDE + nl] = (nt < n) ? g_a2[nt * 64 + k] : 0.0f;
    }
    if (t < MB) {
        int nt = base + t;
        sB[t] = (nt < n) ? ld_idx(batch, nt, g_is64) : -1;
    }
    __syncthreads();

    int tx = t & 31;   // feature group: features tx*4 .. tx*4+3
    int ty = t >> 5;   // node group:    nodes ty*8 .. ty*8+7 (local)

    unsigned long long accp[NQ][2];   // [node q][feature pair]
    #pragma unroll
    for (int q = 0; q < NQ; q++) { accp[q][0] = 0ull; accp[q][1] = 0ull; }

    #pragma unroll 2
    for (int k = 0; k < 64; k++) {
        float4 wv = *(const float4*)&sW[k * 128 + tx * 4];
        ulonglong2 wp = *reinterpret_cast<ulonglong2*>(&wv);   // {w0,w1},{w2,w3}
        float4 av0 = *(const float4*)&sAT[k * AT_STRIDE + ty * 8];
        float4 av1 = *(const float4*)&sAT[k * AT_STRIDE + ty * 8 + 4];
        float aq[NQ] = {av0.x, av0.y, av0.z, av0.w, av1.x, av1.y, av1.z, av1.w};
        #pragma unroll
        for (int q = 0; q < NQ; q++) {
            unsigned long long ad;
            asm("mov.b64 %0, {%1, %1};" : "=l"(ad) : "f"(aq[q]));
            asm("fma.rn.f32x2 %0, %1, %2, %0;" : "+l"(accp[q][0]) : "l"(ad), "l"(wp.x));
            asm("fma.rn.f32x2 %0, %1, %2, %0;" : "+l"(accp[q][1]) : "l"(ad), "l"(wp.y));
        }
    }

    float bias0 = b2[tx * 4], bias1 = b2[tx * 4 + 1];
    float bias2 = b2[tx * 4 + 2], bias3 = b2[tx * 4 + 3];

    // unpack + relu
    float y[NQ][4];
    #pragma unroll
    for (int q = 0; q < NQ; q++) {
        float l0, h0, l1, h1;
        asm("mov.b64 {%0, %1}, %2;" : "=f"(l0), "=f"(h0) : "l"(accp[q][0]));
        asm("mov.b64 {%0, %1}, %2;" : "=f"(l1), "=f"(h1) : "l"(accp[q][1]));
        y[q][0] = fmaxf(l0 + bias0, 0.0f);
        y[q][1] = fmaxf(h0 + bias1, 0.0f);
        y[q][2] = fmaxf(l1 + bias2, 0.0f);
        y[q][3] = fmaxf(h1 + bias3, 0.0f);
    }

    // run-length pooled atomics over this thread's NQ (sorted-batch) nodes
    int cur = -1;
    float run0 = 0, run1 = 0, run2 = 0, run3 = 0;
    #pragma unroll
    for (int q = 0; q < NQ; q++) {
        int g = sB[ty * NQ + q];
        if (g != cur) {
            if (cur >= 0) {
                float* p = &g_pool[cur * 128 + tx * 4];
                atomicAdd(p, run0); atomicAdd(p + 1, run1);
                atomicAdd(p + 2, run2); atomicAdd(p + 3, run3);
            }
            cur = g; run0 = y[q][0]; run1 = y[q][1]; run2 = y[q][2]; run3 = y[q][3];
        } else {
            run0 += y[q][0]; run1 += y[q][1]; run2 += y[q][2]; run3 += y[q][3];
        }
    }
    if (cur >= 0) {
        float* p = &g_pool[cur * 128 + tx * 4];
        atomicAdd(p, run0); atomicAdd(p + 1, run1);
        atomicAdd(p + 2, run2); atomicAdd(p + 3, run3);
    }

    if (t == 0) {
        int rc = 0, cg = -1;
        for (int q = 0; q < MB; q++) {
            int g = sB[q];
            if (g != cg) {
                if (cg >= 0) atomicAdd(&g_gcnt[cg], rc);
                cg = g; rc = (g >= 0) ? 1 : 0;
            } else if (g >= 0) rc++;
        }
        if (cg >= 0) atomicAdd(&g_gcnt[cg], rc);
    }
}

// ---------------- head: mean, fc1+relu, fc2 --------------------------------------
__global__ void k_head(const float* __restrict__ fc1W, const float* __restrict__ fc1b,
                       const float* __restrict__ fc2W, const float* __restrict__ fc2b,
                       float* __restrict__ out) {
    int g = blockIdx.x;
    int t = threadIdx.x;  // 128
    __shared__ float sv[128];
    __shared__ float red[64];
    float denom = fmaxf((float)g_gcnt[g], 1.0f);
    sv[t] = g_pool[g * 128 + t] / denom;
    __syncthreads();
    if (t < 64) {
        float a = fc1b[t];
        #pragma unroll 8
        for (int k = 0; k < 128; k++) a = fmaf(sv[k], fc1W[k * 64 + t], a);
        red[t] = fmaxf(a, 0.0f) * fc2W[t];
    }
    __syncthreads();
    if (t < 32) {
        float v = red[t] + red[t + 32];
        #pragma unroll
        for (int o = 16; o > 0; o >>= 1) v += __shfl_down_sync(0xffffffffu, v, o);
        if (t == 0) out[g] = v + fc2b[0];
    }
}

// ---------------- launch ----------------------------------------------------------
extern "C" void kernel_launch(void* const* d_in, const int* in_sizes, int n_in,
                              void* d_out, int out_size) {
    const float* x     = (const float*)d_in[0];
    const void*  ei    = d_in[1];
    const void*  batch = d_in[2];
    const float* W1    = (const float*)d_in[3];
    const float* b1    = (const float*)d_in[4];
    const float* W2    = (const float*)d_in[5];
    const float* b2    = (const float*)d_in[6];
    const float* fc1W  = (const float*)d_in[7];
    const float* fc1b  = (const float*)d_in[8];
    const float* fc2W  = (const float*)d_in[9];
    const float* fc2b  = (const float*)d_in[10];
    float* out = (float*)d_out;

    int N = in_sizes[0] / 4;   // 100000
    int E = in_sizes[1] / 2;   // 1600000

    k_detect<<<1, 32>>>((const unsigned int*)ei);

    int zmax = NG * 128;  // 131072 > NN
    k_zero<<<(zmax + 255) / 256, 256>>>();

    k_count<<<(E + 511) / 512, 512>>>(ei, E);

    int nb = (N + SCAN_B - 1) / SCAN_B;   // 98
    k_scan1<<<nb, SCAN_B>>>(N);
    k_scan2<<<1, 128>>>(nb);
    k_scan3<<<nb, SCAN_B>>>(x, N);

    k_fill<<<(E + 511) / 512, 512>>>(ei, E);

    k_l1<<<(N + 127) / 128, 128>>>(W1, b1, N);

    dim3 bt2(32, 8);
    k_agg2<<<(N + 7) / 8, bt2>>>(N);

    k_gemm2pool<<<(N + MB - 1) / MB, 256>>>(W2, b2, batch, N);

    k_head<<<NG, 128>>>(fc1W, fc1b, fc2W, fc2b, out);
}